// round 3
// baseline (speedup 1.0000x reference)
#include <cuda_runtime.h>
#include <cuda_bf16.h>
#include <cstddef>

// Problem constants
// B=8, C=1024, Ci=512, N=2048 (=8*16*16)
constexpr int Bn   = 8;
constexpr int C    = 1024;
constexpr int Ci   = 512;
constexpr int NSP  = 2048;

constexpr int BM = 128, BNt = 128, BK = 8, THREADS = 256;

// Scratch (static __device__ arrays are the sanctioned scratch mechanism)
__device__ float d_proj[(size_t)Bn * (3 * Ci) * NSP];  // (8,1536,2048) ~100 MB : [g | theta | phi]
__device__ float d_f[(size_t)Bn * NSP * NSP];          // (8,2048,2048) ~134 MB : scores / probs
__device__ float d_y[(size_t)Bn * Ci * NSP];           // (8,512,2048)  ~33 MB

// ---------------------------------------------------------------------------
// Kernel 1: fused projections.  proj[b][o][n] = sum_c W[o][c] * x[b][c][n] + bias[o]
// o in [0,1536): rows 0-511 = g, 512-1023 = theta, 1024-1535 = phi.
// A (weights) is (512,1024) row-major -> transpose-load; B = x (1024,2048) direct.
// ---------------------------------------------------------------------------
__global__ __launch_bounds__(THREADS)
void k_proj(const float* __restrict__ x,
            const float* __restrict__ gw, const float* __restrict__ gb,
            const float* __restrict__ tw, const float* __restrict__ tb,
            const float* __restrict__ pw, const float* __restrict__ pb)
{
    __shared__ float As[2][BK][BM];
    __shared__ float Bs[2][BK][BNt];

    const int tid = threadIdx.x;
    const int n0  = blockIdx.x * BNt;
    const int mt  = blockIdx.y;            // 0..11
    const int b   = blockIdx.z;

    const float *W, *bias;
    if (mt < 4)      { W = gw; bias = gb; }
    else if (mt < 8) { W = tw; bias = tb; }
    else             { W = pw; bias = pb; }
    const int mloc = (mt & 3) * BM;        // row offset inside the 512-row weight

    const float* Aptr = W + (size_t)mloc * C;
    const float* Bptr = x + (size_t)b * C * NSP;
    float*       Cptr = d_proj + ((size_t)b * (3 * Ci) + (size_t)mt * BM) * NSP;

    const int a_r = tid >> 1;              // 0..127 (m row)
    const int a_k = (tid & 1) * 4;         // 0 or 4
    const int b_k = tid >> 5;              // 0..7
    const int b_c = (tid & 31) * 4;        // 0..124

    {   // preload k-tile 0
        float4 va = *(const float4*)(Aptr + (size_t)a_r * C + a_k);
        As[0][a_k+0][a_r] = va.x; As[0][a_k+1][a_r] = va.y;
        As[0][a_k+2][a_r] = va.z; As[0][a_k+3][a_r] = va.w;
        *(float4*)&Bs[0][b_k][b_c] = *(const float4*)(Bptr + (size_t)b_k * NSP + n0 + b_c);
    }
    __syncthreads();

    float acc[8][8];
    #pragma unroll
    for (int i = 0; i < 8; i++)
        #pragma unroll
        for (int j = 0; j < 8; j++) acc[i][j] = 0.f;

    const int trow = (tid >> 4) * 8;
    const int tcol = (tid & 15) * 8;
    const int KT = C / BK;                 // 128

    for (int kt = 0; kt < KT; ++kt) {
        const int buf = kt & 1;
        float4 va, vb;
        const bool more = (kt + 1 < KT);
        if (more) {
            const int k0 = (kt + 1) * BK;
            va = *(const float4*)(Aptr + (size_t)a_r * C + k0 + a_k);
            vb = *(const float4*)(Bptr + (size_t)(k0 + b_k) * NSP + n0 + b_c);
        }
        #pragma unroll
        for (int k = 0; k < BK; ++k) {
            float a[8], bb[8];
            *(float4*)&a[0]  = *(const float4*)&As[buf][k][trow];
            *(float4*)&a[4]  = *(const float4*)&As[buf][k][trow + 4];
            *(float4*)&bb[0] = *(const float4*)&Bs[buf][k][tcol];
            *(float4*)&bb[4] = *(const float4*)&Bs[buf][k][tcol + 4];
            #pragma unroll
            for (int i = 0; i < 8; i++)
                #pragma unroll
                for (int j = 0; j < 8; j++)
                    acc[i][j] += a[i] * bb[j];
        }
        if (more) {
            const int nb = buf ^ 1;
            As[nb][a_k+0][a_r] = va.x; As[nb][a_k+1][a_r] = va.y;
            As[nb][a_k+2][a_r] = va.z; As[nb][a_k+3][a_r] = va.w;
            *(float4*)&Bs[nb][b_k][b_c] = vb;
        }
        __syncthreads();
    }

    #pragma unroll
    for (int i = 0; i < 8; i++) {
        const float bv = bias[mloc + trow + i];
        float* crow = Cptr + (size_t)(trow + i) * NSP + n0 + tcol;
        float4 o0 = { acc[i][0]+bv, acc[i][1]+bv, acc[i][2]+bv, acc[i][3]+bv };
        float4 o1 = { acc[i][4]+bv, acc[i][5]+bv, acc[i][6]+bv, acc[i][7]+bv };
        *(float4*)(crow)     = o0;
        *(float4*)(crow + 4) = o1;
    }
}

// ---------------------------------------------------------------------------
// Kernel 2: scores.  f[b][n][m] = sum_c theta[b][c][n] * phi[b][c][m]
// Both operands (K=512, 2048) with the 2048-dim contiguous -> direct loads.
// ---------------------------------------------------------------------------
__global__ __launch_bounds__(THREADS)
void k_scores()
{
    __shared__ float As[2][BK][BM];
    __shared__ float Bs[2][BK][BNt];

    const int tid = threadIdx.x;
    const int m0  = blockIdx.x * BNt;      // phi spatial (cols of f)
    const int r0  = blockIdx.y * BM;       // theta spatial (rows of f)
    const int b   = blockIdx.z;

    const float* Aptr = d_proj + ((size_t)b * (3 * Ci) + Ci)     * NSP;  // theta
    const float* Bptr = d_proj + ((size_t)b * (3 * Ci) + 2 * Ci) * NSP;  // phi
    float*       Cptr = d_f + (size_t)b * NSP * NSP;

    const int l_k = tid >> 5;              // 0..7
    const int l_c = (tid & 31) * 4;        // 0..124

    {
        *(float4*)&As[0][l_k][l_c] = *(const float4*)(Aptr + (size_t)l_k * NSP + r0 + l_c);
        *(float4*)&Bs[0][l_k][l_c] = *(const float4*)(Bptr + (size_t)l_k * NSP + m0 + l_c);
    }
    __syncthreads();

    float acc[8][8];
    #pragma unroll
    for (int i = 0; i < 8; i++)
        #pragma unroll
        for (int j = 0; j < 8; j++) acc[i][j] = 0.f;

    const int trow = (tid >> 4) * 8;
    const int tcol = (tid & 15) * 8;
    const int KT = Ci / BK;                // 64

    for (int kt = 0; kt < KT; ++kt) {
        const int buf = kt & 1;
        float4 va, vb;
        const bool more = (kt + 1 < KT);
        if (more) {
            const int k0 = (kt + 1) * BK;
            va = *(const float4*)(Aptr + (size_t)(k0 + l_k) * NSP + r0 + l_c);
            vb = *(const float4*)(Bptr + (size_t)(k0 + l_k) * NSP + m0 + l_c);
        }
        #pragma unroll
        for (int k = 0; k < BK; ++k) {
            float a[8], bb[8];
            *(float4*)&a[0]  = *(const float4*)&As[buf][k][trow];
            *(float4*)&a[4]  = *(const float4*)&As[buf][k][trow + 4];
            *(float4*)&bb[0] = *(const float4*)&Bs[buf][k][tcol];
            *(float4*)&bb[4] = *(const float4*)&Bs[buf][k][tcol + 4];
            #pragma unroll
            for (int i = 0; i < 8; i++)
                #pragma unroll
                for (int j = 0; j < 8; j++)
                    acc[i][j] += a[i] * bb[j];
        }
        if (more) {
            const int nb = buf ^ 1;
            *(float4*)&As[nb][l_k][l_c] = va;
            *(float4*)&Bs[nb][l_k][l_c] = vb;
        }
        __syncthreads();
    }

    #pragma unroll
    for (int i = 0; i < 8; i++) {
        float* crow = Cptr + (size_t)(r0 + trow + i) * NSP + m0 + tcol;
        *(float4*)(crow)     = *(float4*)&acc[i][0];
        *(float4*)(crow + 4) = *(float4*)&acc[i][4];
    }
}

// ---------------------------------------------------------------------------
// Kernel 3: row softmax, in place on d_f. 16384 rows of 2048.
// ---------------------------------------------------------------------------
__global__ __launch_bounds__(THREADS)
void k_softmax()
{
    const int tid = threadIdx.x;
    float* row = d_f + (size_t)blockIdx.x * NSP;

    float v[8];
    #pragma unroll
    for (int i = 0; i < 8; i++) v[i] = row[tid + 256 * i];

    float m = v[0];
    #pragma unroll
    for (int i = 1; i < 8; i++) m = fmaxf(m, v[i]);
    #pragma unroll
    for (int o = 16; o; o >>= 1) m = fmaxf(m, __shfl_xor_sync(0xffffffffu, m, o));

    __shared__ float redm[8];
    __shared__ float reds[8];
    const int wid = tid >> 5, lane = tid & 31;
    if (lane == 0) redm[wid] = m;
    __syncthreads();
    m = redm[0];
    #pragma unroll
    for (int i = 1; i < 8; i++) m = fmaxf(m, redm[i]);

    float s = 0.f;
    #pragma unroll
    for (int i = 0; i < 8; i++) { v[i] = __expf(v[i] - m); s += v[i]; }
    #pragma unroll
    for (int o = 16; o; o >>= 1) s += __shfl_xor_sync(0xffffffffu, s, o);
    if (lane == 0) reds[wid] = s;
    __syncthreads();
    s = reds[0];
    #pragma unroll
    for (int i = 1; i < 8; i++) s += reds[i];

    const float inv = 1.0f / s;
    #pragma unroll
    for (int i = 0; i < 8; i++) row[tid + 256 * i] = v[i] * inv;
}

// ---------------------------------------------------------------------------
// Kernel 4: attention apply.  y[b][ci][n] = sum_m g[b][ci][m] * P[b][n][m]
// A = g (512 rows, 2048 cols m) row-major -> transpose-load (k = m).
// B = P (2048 rows n, 2048 cols m)       -> transpose-load (k = m).
// ---------------------------------------------------------------------------
__global__ __launch_bounds__(THREADS)
void k_ygemm()
{
    __shared__ float As[2][BK][BM];
    __shared__ float Bs[2][BK][BNt];

    const int tid = threadIdx.x;
    const int n0  = blockIdx.x * BNt;      // n (cols of y)
    const int c0  = blockIdx.y * BM;       // ci (rows of y)
    const int b   = blockIdx.z;

    const float* Aptr = d_proj + (size_t)b * (3 * Ci) * NSP;  // g: (512, 2048)
    const float* Bptr = d_f + (size_t)b * NSP * NSP;          // P: (2048, 2048)
    float*       Cptr = d_y + (size_t)b * Ci * NSP;

    const int a_r = tid >> 1;              // 0..127
    const int a_k = (tid & 1) * 4;

    {
        float4 va = *(const float4*)(Aptr + (size_t)(c0 + a_r) * NSP + a_k);
        As[0][a_k+0][a_r] = va.x; As[0][a_k+1][a_r] = va.y;
        As[0][a_k+2][a_r] = va.z; As[0][a_k+3][a_r] = va.w;
        float4 vb = *(const float4*)(Bptr + (size_t)(n0 + a_r) * NSP + a_k);
        Bs[0][a_k+0][a_r] = vb.x; Bs[0][a_k+1][a_r] = vb.y;
        Bs[0][a_k+2][a_r] = vb.z; Bs[0][a_k+3][a_r] = vb.w;
    }
    __syncthreads();

    float acc[8][8];
    #pragma unroll
    for (int i = 0; i < 8; i++)
        #pragma unroll
        for (int j = 0; j < 8; j++) acc[i][j] = 0.f;

    const int trow = (tid >> 4) * 8;
    const int tcol = (tid & 15) * 8;
    const int KT = NSP / BK;               // 256

    for (int kt = 0; kt < KT; ++kt) {
        const int buf = kt & 1;
        float4 va, vb;
        const bool more = (kt + 1 < KT);
        if (more) {
            const int k0 = (kt + 1) * BK;
            va = *(const float4*)(Aptr + (size_t)(c0 + a_r) * NSP + k0 + a_k);
            vb = *(const float4*)(Bptr + (size_t)(n0 + a_r) * NSP + k0 + a_k);
        }
        #pragma unroll
        for (int k = 0; k < BK; ++k) {
            float a[8], bb[8];
            *(float4*)&a[0]  = *(const float4*)&As[buf][k][trow];
            *(float4*)&a[4]  = *(const float4*)&As[buf][k][trow + 4];
            *(float4*)&bb[0] = *(const float4*)&Bs[buf][k][tcol];
            *(float4*)&bb[4] = *(const float4*)&Bs[buf][k][tcol + 4];
            #pragma unroll
            for (int i = 0; i < 8; i++)
                #pragma unroll
                for (int j = 0; j < 8; j++)
                    acc[i][j] += a[i] * bb[j];
        }
        if (more) {
            const int nb = buf ^ 1;
            As[nb][a_k+0][a_r] = va.x; As[nb][a_k+1][a_r] = va.y;
            As[nb][a_k+2][a_r] = va.z; As[nb][a_k+3][a_r] = va.w;
            Bs[nb][a_k+0][a_r] = vb.x; Bs[nb][a_k+1][a_r] = vb.y;
            Bs[nb][a_k+2][a_r] = vb.z; Bs[nb][a_k+3][a_r] = vb.w;
        }
        __syncthreads();
    }

    #pragma unroll
    for (int i = 0; i < 8; i++) {
        float* crow = Cptr + (size_t)(c0 + trow + i) * NSP + n0 + tcol;
        *(float4*)(crow)     = *(float4*)&acc[i][0];
        *(float4*)(crow + 4) = *(float4*)&acc[i][4];
    }
}

// ---------------------------------------------------------------------------
// Kernel 5: output GEMM + bias + BatchNorm(inference) + residual.
// z[b][c][n] = BN( sum_ci W_w[c][ci] * y[b][ci][n] + W_b[c] ) + x[b][c][n]
// ---------------------------------------------------------------------------
__global__ __launch_bounds__(THREADS)
void k_final(const float* __restrict__ Ww, const float* __restrict__ Wb,
             const float* __restrict__ gamma, const float* __restrict__ beta,
             const float* __restrict__ mean,  const float* __restrict__ var,
             const float* __restrict__ x, float* __restrict__ out)
{
    __shared__ float As[2][BK][BM];
    __shared__ float Bs[2][BK][BNt];

    const int tid = threadIdx.x;
    const int n0  = blockIdx.x * BNt;
    const int c0  = blockIdx.y * BM;       // output channel tile (of 1024)
    const int b   = blockIdx.z;

    const float* Aptr = Ww;                             // (1024, 512) row-major
    const float* Bptr = d_y + (size_t)b * Ci * NSP;     // (512, 2048)

    const int a_r = tid >> 1;
    const int a_k = (tid & 1) * 4;
    const int b_k = tid >> 5;
    const int b_c = (tid & 31) * 4;

    {
        float4 va = *(const float4*)(Aptr + (size_t)(c0 + a_r) * Ci + a_k);
        As[0][a_k+0][a_r] = va.x; As[0][a_k+1][a_r] = va.y;
        As[0][a_k+2][a_r] = va.z; As[0][a_k+3][a_r] = va.w;
        *(float4*)&Bs[0][b_k][b_c] = *(const float4*)(Bptr + (size_t)b_k * NSP + n0 + b_c);
    }
    __syncthreads();

    float acc[8][8];
    #pragma unroll
    for (int i = 0; i < 8; i++)
        #pragma unroll
        for (int j = 0; j < 8; j++) acc[i][j] = 0.f;

    const int trow = (tid >> 4) * 8;
    const int tcol = (tid & 15) * 8;
    const int KT = Ci / BK;                // 64

    for (int kt = 0; kt < KT; ++kt) {
        const int buf = kt & 1;
        float4 va, vb;
        const bool more = (kt + 1 < KT);
        if (more) {
            const int k0 = (kt + 1) * BK;
            va = *(const float4*)(Aptr + (size_t)(c0 + a_r) * Ci + k0 + a_k);
            vb = *(const float4*)(Bptr + (size_t)(k0 + b_k) * NSP + n0 + b_c);
        }
        #pragma unroll
        for (int k = 0; k < BK; ++k) {
            float a[8], bb[8];
            *(float4*)&a[0]  = *(const float4*)&As[buf][k][trow];
            *(float4*)&a[4]  = *(const float4*)&As[buf][k][trow + 4];
            *(float4*)&bb[0] = *(const float4*)&Bs[buf][k][tcol];
            *(float4*)&bb[4] = *(const float4*)&Bs[buf][k][tcol + 4];
            #pragma unroll
            for (int i = 0; i < 8; i++)
                #pragma unroll
                for (int j = 0; j < 8; j++)
                    acc[i][j] += a[i] * bb[j];
        }
        if (more) {
            const int nb = buf ^ 1;
            As[nb][a_k+0][a_r] = va.x; As[nb][a_k+1][a_r] = va.y;
            As[nb][a_k+2][a_r] = va.z; As[nb][a_k+3][a_r] = va.w;
            *(float4*)&Bs[nb][b_k][b_c] = vb;
        }
        __syncthreads();
    }

    #pragma unroll
    for (int i = 0; i < 8; i++) {
        const int c = c0 + trow + i;
        const float sgl = rsqrtf(var[c] + 1e-5f) * gamma[c];
        const float off = (Wb[c] - mean[c]) * sgl + beta[c];
        const size_t base = ((size_t)b * C + c) * NSP + n0 + tcol;
        const float4 x0 = *(const float4*)(x + base);
        const float4 x1 = *(const float4*)(x + base + 4);
        float4 o0 = { acc[i][0]*sgl + off + x0.x, acc[i][1]*sgl + off + x0.y,
                      acc[i][2]*sgl + off + x0.z, acc[i][3]*sgl + off + x0.w };
        float4 o1 = { acc[i][4]*sgl + off + x1.x, acc[i][5]*sgl + off + x1.y,
                      acc[i][6]*sgl + off + x1.z, acc[i][7]*sgl + off + x1.w };
        *(float4*)(out + base)     = o0;
        *(float4*)(out + base + 4) = o1;
    }
}

// ---------------------------------------------------------------------------
extern "C" void kernel_launch(void* const* d_in, const int* in_sizes, int n_in,
                              void* d_out, int out_size)
{
    const float* x     = (const float*)d_in[0];
    const float* g_w   = (const float*)d_in[1];
    const float* g_b   = (const float*)d_in[2];
    const float* th_w  = (const float*)d_in[3];
    const float* th_b  = (const float*)d_in[4];
    const float* ph_w  = (const float*)d_in[5];
    const float* ph_b  = (const float*)d_in[6];
    const float* W_w   = (const float*)d_in[7];
    const float* W_b   = (const float*)d_in[8];
    const float* gamma = (const float*)d_in[9];
    const float* beta  = (const float*)d_in[10];
    const float* mean  = (const float*)d_in[11];
    const float* var   = (const float*)d_in[12];
    float* out = (float*)d_out;

    dim3 blk(THREADS);
    k_proj   <<<dim3(NSP / BNt, 12, Bn), blk>>>(x, g_w, g_b, th_w, th_b, ph_w, ph_b);
    k_scores <<<dim3(NSP / BNt, NSP / BM, Bn), blk>>>();
    k_softmax<<<dim3(Bn * NSP), blk>>>();
    k_ygemm  <<<dim3(NSP / BNt, Ci / BM, Bn), blk>>>();
    k_final  <<<dim3(NSP / BNt, C / BM, Bn), blk>>>(W_w, W_b, gamma, beta, mean, var, x, out);
}

// round 5
// speedup vs baseline: 2.1754x; 2.1754x over previous
#include <cuda_runtime.h>
#include <cuda_bf16.h>
#include <cstddef>

// B=8, C=1024, Ci=512, N=T*H*W=2048
constexpr int Bn   = 8;
constexpr int C    = 1024;
constexpr int Ci   = 512;
constexpr int NSP  = 2048;

constexpr int TPB = 256;          // 8 warps, warp grid 2x4, warp tile 64x32
// bf16 smem tile strides
constexpr int ANS = 24;           // natural [row][k16] tile stride (bf16) -> 12 words, conflict-free
constexpr int ANE = 128 * ANS;    // 3072 bf16 per plane
constexpr int KMS = 136;          // k-major [k16][col128] stride (bf16) -> conflict-free ldsm
constexpr int KME = 16 * KMS;     // 2176 bf16 per plane

// fp32 scratch
__device__ float d_proj[(size_t)Bn * (3 * Ci) * NSP];  // [g | theta | phi]
__device__ float d_f[(size_t)Bn * NSP * NSP];          // scores / probs
__device__ float d_y[(size_t)Bn * Ci * NSP];

// ---------------------------------------------------------------------------
__device__ __forceinline__ unsigned smaddr(const void* p) {
    return (unsigned)__cvta_generic_to_shared(p);
}

__device__ __forceinline__ void ldsm4t(const void* p, unsigned& r0, unsigned& r1,
                                       unsigned& r2, unsigned& r3) {
    asm volatile("ldmatrix.sync.aligned.m8n8.x4.trans.shared.b16 {%0,%1,%2,%3}, [%4];"
                 : "=r"(r0), "=r"(r1), "=r"(r2), "=r"(r3) : "r"(smaddr(p)));
}

__device__ __forceinline__ void mma_bf(float* c, const unsigned* a, unsigned b0, unsigned b1) {
    asm volatile(
        "mma.sync.aligned.m16n8k16.row.col.f32.bf16.bf16.f32 "
        "{%0,%1,%2,%3}, {%4,%5,%6,%7}, {%8,%9}, {%0,%1,%2,%3};"
        : "+f"(c[0]), "+f"(c[1]), "+f"(c[2]), "+f"(c[3])
        : "r"(a[0]), "r"(a[1]), "r"(a[2]), "r"(a[3]), "r"(b0), "r"(b1));
}

// Split 4 fp32 into hi/lo bf16 quads (packed, 8B each).
__device__ __forceinline__ void split4(float4 v, uint2& h, uint2& l) {
    __nv_bfloat162 h0 = __floats2bfloat162_rn(v.x, v.y);
    __nv_bfloat162 h1 = __floats2bfloat162_rn(v.z, v.w);
    __nv_bfloat162 l0 = __floats2bfloat162_rn(v.x - __bfloat162float(h0.x),
                                              v.y - __bfloat162float(h0.y));
    __nv_bfloat162 l1 = __floats2bfloat162_rn(v.z - __bfloat162float(h1.x),
                                              v.w - __bfloat162float(h1.y));
    h.x = *reinterpret_cast<unsigned*>(&h0);
    h.y = *reinterpret_cast<unsigned*>(&h1);
    l.x = *reinterpret_cast<unsigned*>(&l0);
    l.y = *reinterpret_cast<unsigned*>(&l1);
}

// --- global loads (fp32, float4 x2 per thread per tile) --------------------
__device__ __forceinline__ void ldg_nat(const float* __restrict__ A, int lda, int tid,
                                        int kglob, float4& v0, float4& v1) {
    const int row = tid >> 1, kl = (tid & 1) * 8;
    const float* p = A + (size_t)row * lda + kglob + kl;
    v0 = *(const float4*)p; v1 = *(const float4*)(p + 4);
}
__device__ __forceinline__ void ldg_km(const float* __restrict__ B, int ldb, int tid,
                                       int kglob, int d0, float4& v0, float4& v1) {
    const int k = tid >> 4, nq = (tid & 15) * 4;
    const float* p = B + (size_t)(kglob + k) * ldb + d0 + nq;
    v0 = *(const float4*)p; v1 = *(const float4*)(p + 64);
}
__device__ __forceinline__ void ldg_tr(const float* __restrict__ P, int ldp, int tid,
                                       int kglob, int n0, float4& v0, float4& v1) {
    const int n = tid >> 1, mq = (tid & 1) * 8;
    const float* p = P + (size_t)(n0 + n) * ldp + kglob + mq;
    v0 = *(const float4*)p; v1 = *(const float4*)(p + 4);
}

// --- smem stores (split into hi/lo planes) ---------------------------------
// natural: (row=tid>>1, kbase=(tid&1)*8); also used for P [n][k] tiles.
__device__ __forceinline__ void sts_nat(unsigned short* H, unsigned short* L,
                                        int tid, float4 v0, float4 v1) {
    const int idx = (tid >> 1) * ANS + (tid & 1) * 8;
    uint2 h, l;
    split4(v0, h, l); *(uint2*)(H + idx) = h;     *(uint2*)(L + idx) = l;
    split4(v1, h, l); *(uint2*)(H + idx + 4) = h; *(uint2*)(L + idx + 4) = l;
}
// k-major: (k=tid>>4, nq=(tid&15)*4), second quad at col +64
__device__ __forceinline__ void sts_km(unsigned short* H, unsigned short* L,
                                       int tid, float4 v0, float4 v1) {
    const int idx = (tid >> 4) * KMS + (tid & 15) * 4;
    uint2 h, l;
    split4(v0, h, l); *(uint2*)(H + idx) = h;      *(uint2*)(L + idx) = l;
    split4(v1, h, l); *(uint2*)(H + idx + 64) = h; *(uint2*)(L + idx + 64) = l;
}

// --- fragment gathers ------------------------------------------------------
// A from natural [m][k16] stride 24 bf16 (12 words), plain LDS.32, conflict-free.
__device__ __forceinline__ void frag_a_nat(const unsigned short* S, int m_base,
                                           int gid, int tig, unsigned* a) {
    const unsigned* w = (const unsigned*)S;
    const int r = m_base + gid;
    a[0] = w[r * 12 + tig];
    a[1] = w[(r + 8) * 12 + tig];
    a[2] = w[r * 12 + tig + 4];
    a[3] = w[(r + 8) * 12 + tig + 4];
}
// A from k-major [k16][m128] stride 136: ldsm.x4.trans, reorder {r0,r2,r1,r3}.
__device__ __forceinline__ void frag_a_kmt(const unsigned short* S, int m_base,
                                           int lane, unsigned* a) {
    const int k  = (lane & 7) + ((lane >> 3) & 1) * 8;
    const int mc = m_base + (lane >> 4) * 8;
    unsigned r0, r1, r2, r3;
    ldsm4t(S + k * KMS + mc, r0, r1, r2, r3);
    a[0] = r0; a[1] = r2; a[2] = r1; a[3] = r3;
}
// B from k-major: ldsm.x4.trans covers n16 -> {b0(j0),b1(j0),b0(j1),b1(j1)}.
__device__ __forceinline__ void frag_b_kmt(const unsigned short* S, int n_base,
                                           int lane, unsigned* b) {
    const int k  = (lane & 7) + ((lane >> 3) & 1) * 8;
    const int nc = n_base + (lane >> 4) * 8;
    ldsm4t(S + k * KMS + nc, b[0], b[1], b[2], b[3]);
}
// B from natural [n][k16] stride 24: plain LDS.32 (pairs contiguous along k).
__device__ __forceinline__ void frag_b_nat(const unsigned short* S, int n_base,
                                           int gid, int tig, unsigned* b) {
    const unsigned* w = (const unsigned*)S;
    const int n = n_base + gid;
    b[0] = w[n * 12 + tig];
    b[1] = w[n * 12 + tig + 4];
}

#define ACC_INIT(acc)                                        \
    float acc[4][4][4];                                      \
    _Pragma("unroll") for (int i = 0; i < 4; ++i)            \
    _Pragma("unroll") for (int j = 0; j < 4; ++j)            \
    _Pragma("unroll") for (int q = 0; q < 4; ++q) acc[i][j][q] = 0.f;

// 3xBF16 compute: A natural, B k-major
__device__ __forceinline__ void comp_nat_kmt(const unsigned short* Ah, const unsigned short* Al,
                                             const unsigned short* Bh, const unsigned short* Bl,
                                             int lane, int wm, int wn, float (&acc)[4][4][4]) {
    const int gid = lane >> 2, tig = lane & 3;
    unsigned ah[4][4], al[4][4];
    #pragma unroll
    for (int i = 0; i < 4; ++i) {
        frag_a_nat(Ah, wm + i * 16, gid, tig, ah[i]);
        frag_a_nat(Al, wm + i * 16, gid, tig, al[i]);
    }
    #pragma unroll
    for (int jj = 0; jj < 2; ++jj) {
        unsigned bh[4], bl[4];
        frag_b_kmt(Bh, wn + jj * 16, lane, bh);
        frag_b_kmt(Bl, wn + jj * 16, lane, bl);
        #pragma unroll
        for (int jr = 0; jr < 2; ++jr) {
            const int j = jj * 2 + jr;
            #pragma unroll
            for (int i = 0; i < 4; ++i) {
                mma_bf(acc[i][j], ah[i], bh[jr*2], bh[jr*2+1]);
                mma_bf(acc[i][j], ah[i], bl[jr*2], bl[jr*2+1]);
                mma_bf(acc[i][j], al[i], bh[jr*2], bh[jr*2+1]);
            }
        }
    }
}
// A k-major, B k-major (scores)
__device__ __forceinline__ void comp_kmt_kmt(const unsigned short* Ah, const unsigned short* Al,
                                             const unsigned short* Bh, const unsigned short* Bl,
                                             int lane, int wm, int wn, float (&acc)[4][4][4]) {
    unsigned ah[4][4], al[4][4];
    #pragma unroll
    for (int i = 0; i < 4; ++i) {
        frag_a_kmt(Ah, wm + i * 16, lane, ah[i]);
        frag_a_kmt(Al, wm + i * 16, lane, al[i]);
    }
    #pragma unroll
    for (int jj = 0; jj < 2; ++jj) {
        unsigned bh[4], bl[4];
        frag_b_kmt(Bh, wn + jj * 16, lane, bh);
        frag_b_kmt(Bl, wn + jj * 16, lane, bl);
        #pragma unroll
        for (int jr = 0; jr < 2; ++jr) {
            const int j = jj * 2 + jr;
            #pragma unroll
            for (int i = 0; i < 4; ++i) {
                mma_bf(acc[i][j], ah[i], bh[jr*2], bh[jr*2+1]);
                mma_bf(acc[i][j], ah[i], bl[jr*2], bl[jr*2+1]);
                mma_bf(acc[i][j], al[i], bh[jr*2], bh[jr*2+1]);
            }
        }
    }
}
// A natural, B natural (ygemm)
__device__ __forceinline__ void comp_nat_nat(const unsigned short* Ah, const unsigned short* Al,
                                             const unsigned short* Bh, const unsigned short* Bl,
                                             int lane, int wm, int wn, float (&acc)[4][4][4]) {
    const int gid = lane >> 2, tig = lane & 3;
    unsigned ah[4][4], al[4][4];
    #pragma unroll
    for (int i = 0; i < 4; ++i) {
        frag_a_nat(Ah, wm + i * 16, gid, tig, ah[i]);
        frag_a_nat(Al, wm + i * 16, gid, tig, al[i]);
    }
    #pragma unroll
    for (int j = 0; j < 4; ++j) {
        unsigned bh[2], bl[2];
        frag_b_nat(Bh, wn + j * 8, gid, tig, bh);
        frag_b_nat(Bl, wn + j * 8, gid, tig, bl);
        #pragma unroll
        for (int i = 0; i < 4; ++i) {
            mma_bf(acc[i][j], ah[i], bh[0], bh[1]);
            mma_bf(acc[i][j], ah[i], bl[0], bl[1]);
            mma_bf(acc[i][j], al[i], bh[0], bh[1]);
        }
    }
}

// ---------------------------------------------------------------------------
// Kernel 1: projections. proj[b][o][n] = sum_c W[o][c] x[b][c][n] + bias[o]
// ---------------------------------------------------------------------------
__global__ __launch_bounds__(TPB)
void k_proj(const float* __restrict__ x,
            const float* __restrict__ gw, const float* __restrict__ gb,
            const float* __restrict__ tw, const float* __restrict__ tb,
            const float* __restrict__ pw, const float* __restrict__ pb)
{
    __shared__ __align__(16) unsigned short Ah[2][ANE], Al[2][ANE];
    __shared__ __align__(16) unsigned short Bh[2][KME], Bl[2][KME];

    const int tid = threadIdx.x, lane = tid & 31, wid = tid >> 5;
    const int wm = (wid >> 2) * 64, wn = (wid & 3) * 32;
    const int n0 = blockIdx.x * 128;
    const int mt = blockIdx.y;             // 0..11
    const int b  = blockIdx.z;

    const float *W, *bias;
    if (mt < 4)      { W = gw; bias = gb; }
    else if (mt < 8) { W = tw; bias = tb; }
    else             { W = pw; bias = pb; }
    const int mloc = (mt & 3) * 128;

    const float* Aptr = W + (size_t)mloc * C;
    const float* Bptr = x + (size_t)b * C * NSP;
    float*       Cptr = d_proj + ((size_t)b * (3 * Ci) + (size_t)mt * 128) * NSP;

    float4 a0, a1, b0, b1;
    ldg_nat(Aptr, C, tid, 0, a0, a1);
    ldg_km(Bptr, NSP, tid, 0, n0, b0, b1);
    sts_nat(Ah[0], Al[0], tid, a0, a1);
    sts_km(Bh[0], Bl[0], tid, b0, b1);
    __syncthreads();

    ACC_INIT(acc);
    const int KT = C / 16;                 // 64
    for (int kt = 0; kt < KT; ++kt) {
        const int buf = kt & 1;
        const bool more = (kt + 1 < KT);
        if (more) {
            ldg_nat(Aptr, C, tid, (kt + 1) * 16, a0, a1);
            ldg_km(Bptr, NSP, tid, (kt + 1) * 16, n0, b0, b1);
        }
        comp_nat_kmt(Ah[buf], Al[buf], Bh[buf], Bl[buf], lane, wm, wn, acc);
        if (more) {
            sts_nat(Ah[buf ^ 1], Al[buf ^ 1], tid, a0, a1);
            sts_km(Bh[buf ^ 1], Bl[buf ^ 1], tid, b0, b1);
        }
        __syncthreads();
    }

    const int gid = lane >> 2, tig = lane & 3;
    #pragma unroll
    for (int i = 0; i < 4; ++i) {
        const int r = wm + i * 16 + gid;
        const float bv0 = bias[mloc + r], bv1 = bias[mloc + r + 8];
        #pragma unroll
        for (int j = 0; j < 4; ++j) {
            const int col = n0 + wn + j * 8 + tig * 2;
            float2 o0 = { acc[i][j][0] + bv0, acc[i][j][1] + bv0 };
            float2 o1 = { acc[i][j][2] + bv1, acc[i][j][3] + bv1 };
            *(float2*)(Cptr + (size_t)r * NSP + col)       = o0;
            *(float2*)(Cptr + (size_t)(r + 8) * NSP + col) = o1;
        }
    }
}

// ---------------------------------------------------------------------------
// Kernel 2: scores. f[b][n][m] = sum_c theta[b][c][n] phi[b][c][m]
// ---------------------------------------------------------------------------
__global__ __launch_bounds__(TPB)
void k_scores()
{
    __shared__ __align__(16) unsigned short Ah[2][KME], Al[2][KME];
    __shared__ __align__(16) unsigned short Bh[2][KME], Bl[2][KME];

    const int tid = threadIdx.x, lane = tid & 31, wid = tid >> 5;
    const int wm = (wid >> 2) * 64, wn = (wid & 3) * 32;
    const int m0 = blockIdx.x * 128;
    const int r0 = blockIdx.y * 128;
    const int b  = blockIdx.z;

    const float* Aptr = d_proj + ((size_t)b * (3 * Ci) + Ci)     * NSP; // theta
    const float* Bptr = d_proj + ((size_t)b * (3 * Ci) + 2 * Ci) * NSP; // phi
    float*       Cptr = d_f + (size_t)b * NSP * NSP;

    float4 a0, a1, b0, b1;
    ldg_km(Aptr, NSP, tid, 0, r0, a0, a1);
    ldg_km(Bptr, NSP, tid, 0, m0, b0, b1);
    sts_km(Ah[0], Al[0], tid, a0, a1);
    sts_km(Bh[0], Bl[0], tid, b0, b1);
    __syncthreads();

    ACC_INIT(acc);
    const int KT = Ci / 16;                // 32
    for (int kt = 0; kt < KT; ++kt) {
        const int buf = kt & 1;
        const bool more = (kt + 1 < KT);
        if (more) {
            ldg_km(Aptr, NSP, tid, (kt + 1) * 16, r0, a0, a1);
            ldg_km(Bptr, NSP, tid, (kt + 1) * 16, m0, b0, b1);
        }
        comp_kmt_kmt(Ah[buf], Al[buf], Bh[buf], Bl[buf], lane, wm, wn, acc);
        if (more) {
            sts_km(Ah[buf ^ 1], Al[buf ^ 1], tid, a0, a1);
            sts_km(Bh[buf ^ 1], Bl[buf ^ 1], tid, b0, b1);
        }
        __syncthreads();
    }

    const int gid = lane >> 2, tig = lane & 3;
    #pragma unroll
    for (int i = 0; i < 4; ++i) {
        const int r = r0 + wm + i * 16 + gid;
        #pragma unroll
        for (int j = 0; j < 4; ++j) {
            const int col = m0 + wn + j * 8 + tig * 2;
            *(float2*)(Cptr + (size_t)r * NSP + col)       = *(float2*)&acc[i][j][0];
            *(float2*)(Cptr + (size_t)(r + 8) * NSP + col) = *(float2*)&acc[i][j][2];
        }
    }
}

// ---------------------------------------------------------------------------
// Kernel 3: row softmax in place on d_f.
// ---------------------------------------------------------------------------
__global__ __launch_bounds__(TPB)
void k_softmax()
{
    const int tid = threadIdx.x;
    float* row = d_f + (size_t)blockIdx.x * NSP;

    float v[8];
    #pragma unroll
    for (int i = 0; i < 8; i++) v[i] = row[tid + 256 * i];

    float m = v[0];
    #pragma unroll
    for (int i = 1; i < 8; i++) m = fmaxf(m, v[i]);
    #pragma unroll
    for (int o = 16; o; o >>= 1) m = fmaxf(m, __shfl_xor_sync(0xffffffffu, m, o));

    __shared__ float redm[8], reds[8];
    const int wid = tid >> 5, lane = tid & 31;
    if (lane == 0) redm[wid] = m;
    __syncthreads();
    m = redm[0];
    #pragma unroll
    for (int i = 1; i < 8; i++) m = fmaxf(m, redm[i]);

    float s = 0.f;
    #pragma unroll
    for (int i = 0; i < 8; i++) { v[i] = __expf(v[i] - m); s += v[i]; }
    #pragma unroll
    for (int o = 16; o; o >>= 1) s += __shfl_xor_sync(0xffffffffu, s, o);
    if (lane == 0) reds[wid] = s;
    __syncthreads();
    s = reds[0];
    #pragma unroll
    for (int i = 1; i < 8; i++) s += reds[i];

    const float inv = 1.0f / s;
    #pragma unroll
    for (int i = 0; i < 8; i++) row[tid + 256 * i] = v[i] * inv;
}

// ---------------------------------------------------------------------------
// Kernel 4: apply. y[b][ci][n] = sum_m g[b][ci][m] P[b][n][m]
// A = g natural (k=m contiguous). B = P natural [n][k=m].
// ---------------------------------------------------------------------------
__global__ __launch_bounds__(TPB)
void k_ygemm()
{
    __shared__ __align__(16) unsigned short Ah[2][ANE], Al[2][ANE];
    __shared__ __align__(16) unsigned short Ph[2][ANE], Pl[2][ANE];

    const int tid = threadIdx.x, lane = tid & 31, wid = tid >> 5;
    const int wm = (wid >> 2) * 64, wn = (wid & 3) * 32;
    const int n0 = blockIdx.x * 128;
    const int c0 = blockIdx.y * 128;
    const int b  = blockIdx.z;

    const float* Aptr = d_proj + (size_t)b * (3 * Ci) * NSP + (size_t)c0 * NSP; // g
    const float* Bptr = d_f + (size_t)b * NSP * NSP;                            // P
    float*       Cptr = d_y + (size_t)b * Ci * NSP;

    float4 a0, a1, b0, b1;
    ldg_nat(Aptr, NSP, tid, 0, a0, a1);
    ldg_tr(Bptr, NSP, tid, 0, n0, b0, b1);
    sts_nat(Ah[0], Al[0], tid, a0, a1);
    sts_nat(Ph[0], Pl[0], tid, b0, b1);
    __syncthreads();

    ACC_INIT(acc);
    const int KT = NSP / 16;               // 128
    for (int kt = 0; kt < KT; ++kt) {
        const int buf = kt & 1;
        const bool more = (kt + 1 < KT);
        if (more) {
            ldg_nat(Aptr, NSP, tid, (kt + 1) * 16, a0, a1);
            ldg_tr(Bptr, NSP, tid, (kt + 1) * 16, n0, b0, b1);
        }
        comp_nat_nat(Ah[buf], Al[buf], Ph[buf], Pl[buf], lane, wm, wn, acc);
        if (more) {
            sts_nat(Ah[buf ^ 1], Al[buf ^ 1], tid, a0, a1);
            sts_nat(Ph[buf ^ 1], Pl[buf ^ 1], tid, b0, b1);
        }
        __syncthreads();
    }

    const int gid = lane >> 2, tig = lane & 3;
    #pragma unroll
    for (int i = 0; i < 4; ++i) {
        const int r = c0 + wm + i * 16 + gid;
        #pragma unroll
        for (int j = 0; j < 4; ++j) {
            const int col = n0 + wn + j * 8 + tig * 2;
            *(float2*)(Cptr + (size_t)r * NSP + col)       = *(float2*)&acc[i][j][0];
            *(float2*)(Cptr + (size_t)(r + 8) * NSP + col) = *(float2*)&acc[i][j][2];
        }
    }
}

// ---------------------------------------------------------------------------
// Kernel 5: out GEMM + bias + BN + residual.
// ---------------------------------------------------------------------------
__global__ __launch_bounds__(TPB)
void k_final(const float* __restrict__ Ww, const float* __restrict__ Wb,
             const float* __restrict__ gamma, const float* __restrict__ beta,
             const float* __restrict__ mean,  const float* __restrict__ var,
             const float* __restrict__ x, float* __restrict__ out)
{
    __shared__ __align__(16) unsigned short Ah[2][ANE], Al[2][ANE];
    __shared__ __align__(16) unsigned short Bh[2][KME], Bl[2][KME];

    const int tid = threadIdx.x, lane = tid & 31, wid = tid >> 5;
    const int wm = (wid >> 2) * 64, wn = (wid & 3) * 32;
    const int n0 = blockIdx.x * 128;
    const int c0 = blockIdx.y * 128;
    const int b  = blockIdx.z;

    const float* Aptr = Ww + (size_t)c0 * Ci;
    const float* Bptr = d_y + (size_t)b * Ci * NSP;

    float4 a0, a1, b0, b1;
    ldg_nat(Aptr, Ci, tid, 0, a0, a1);
    ldg_km(Bptr, NSP, tid, 0, n0, b0, b1);
    sts_nat(Ah[0], Al[0], tid, a0, a1);
    sts_km(Bh[0], Bl[0], tid, b0, b1);
    __syncthreads();

    ACC_INIT(acc);
    const int KT = Ci / 16;                // 32
    for (int kt = 0; kt < KT; ++kt) {
        const int buf = kt & 1;
        const bool more = (kt + 1 < KT);
        if (more) {
            ldg_nat(Aptr, Ci, tid, (kt + 1) * 16, a0, a1);
            ldg_km(Bptr, NSP, tid, (kt + 1) * 16, n0, b0, b1);
        }
        comp_nat_kmt(Ah[buf], Al[buf], Bh[buf], Bl[buf], lane, wm, wn, acc);
        if (more) {
            sts_nat(Ah[buf ^ 1], Al[buf ^ 1], tid, a0, a1);
            sts_km(Bh[buf ^ 1], Bl[buf ^ 1], tid, b0, b1);
        }
        __syncthreads();
    }

    const int gid = lane >> 2, tig = lane & 3;
    #pragma unroll
    for (int i = 0; i < 4; ++i) {
        const int ch0 = c0 + wm + i * 16 + gid;
        const int ch1 = ch0 + 8;
        const float sg0 = rsqrtf(var[ch0] + 1e-5f) * gamma[ch0];
        const float of0 = (Wb[ch0] - mean[ch0]) * sg0 + beta[ch0];
        const float sg1 = rsqrtf(var[ch1] + 1e-5f) * gamma[ch1];
        const float of1 = (Wb[ch1] - mean[ch1]) * sg1 + beta[ch1];
        #pragma unroll
        for (int j = 0; j < 4; ++j) {
            const int col = n0 + wn + j * 8 + tig * 2;
            const size_t p0 = ((size_t)b * C + ch0) * NSP + col;
            const size_t p1 = ((size_t)b * C + ch1) * NSP + col;
            const float2 x0 = *(const float2*)(x + p0);
            const float2 x1 = *(const float2*)(x + p1);
            float2 o0 = { acc[i][j][0] * sg0 + of0 + x0.x,
                          acc[i][j][1] * sg0 + of0 + x0.y };
            float2 o1 = { acc[i][j][2] * sg1 + of1 + x1.x,
                          acc[i][j][3] * sg1 + of1 + x1.y };
            *(float2*)(out + p0) = o0;
            *(float2*)(out + p1) = o1;
        }
    }
}

// ---------------------------------------------------------------------------
extern "C" void kernel_launch(void* const* d_in, const int* in_sizes, int n_in,
                              void* d_out, int out_size)
{
    const float* x     = (const float*)d_in[0];
    const float* g_w   = (const float*)d_in[1];
    const float* g_b   = (const float*)d_in[2];
    const float* th_w  = (const float*)d_in[3];
    const float* th_b  = (const float*)d_in[4];
    const float* ph_w  = (const float*)d_in[5];
    const float* ph_b  = (const float*)d_in[6];
    const float* W_w   = (const float*)d_in[7];
    const float* W_b   = (const float*)d_in[8];
    const float* gamma = (const float*)d_in[9];
    const float* beta  = (const float*)d_in[10];
    const float* mean  = (const float*)d_in[11];
    const float* var   = (const float*)d_in[12];
    float* out = (float*)d_out;

    dim3 blk(TPB);
    k_proj   <<<dim3(NSP / 128, 12, Bn), blk>>>(x, g_w, g_b, th_w, th_b, ph_w, ph_b);
    k_scores <<<dim3(NSP / 128, NSP / 128, Bn), blk>>>();
    k_softmax<<<dim3(Bn * NSP), blk>>>();
    k_ygemm  <<<dim3(NSP / 128, Ci / 128, Bn), blk>>>();
    k_final  <<<dim3(NSP / 128, C / 128, Bn), blk>>>(W_w, W_b, gamma, beta, mean, var, x, out);
}